// round 1
// baseline (speedup 1.0000x reference)
#include <cuda_runtime.h>
#include <cuda_bf16.h>
#include <math.h>

#define NTOK  3072
#define UNITS 1024
#define NHEAD 16
#define HDIM  64
#define NBLK  64
#define CHK   32

// Scratch (device globals — no allocation allowed)
__device__ float g_Q[NTOK * UNITS];
__device__ float g_K[NTOK * UNITS];
__device__ float g_V[NTOK * UNITS];
__device__ float g_O[NTOK * UNITS];
__device__ int   g_cnt[NBLK];
__device__ int   g_off[NBLK];
__device__ int   g_mem[NTOK];

// ---------------------------------------------------------------------------
// Build per-block member lists. Deterministic (no atomics): 64 threads, one
// per block; each scans all ids. Trivial cost (64 x 3072 x 2).
// ---------------------------------------------------------------------------
__global__ void build_index_kernel(const int* __restrict__ ids) {
    __shared__ int s_cnt[NBLK];
    int b = threadIdx.x;  // 0..63
    int c = 0;
    for (int i = 0; i < NTOK; i++) c += (ids[i] == b) ? 1 : 0;
    s_cnt[b] = c;
    g_cnt[b] = c;
    __syncthreads();
    if (b == 0) {
        int acc = 0;
        for (int j = 0; j < NBLK; j++) { g_off[j] = acc; acc += s_cnt[j]; }
    }
    __syncthreads();
    int p = g_off[b];
    for (int i = 0; i < NTOK; i++)
        if (ids[i] == b) g_mem[p++] = i;
}

// ---------------------------------------------------------------------------
// SGEMM: C[M,N] = A[M,K] @ B[K,N], row-major fp32.
// BM=128, BN=64, BK=16, 256 threads, 8x4 per thread.
// ---------------------------------------------------------------------------
__global__ __launch_bounds__(256) void sgemm_kernel(
    const float* __restrict__ A, const float* __restrict__ Bm,
    float* __restrict__ C, int M, int Nn, int K)
{
    __shared__ float As[16][128];
    __shared__ float Bs[16][64];

    int t = threadIdx.x;
    int rowBase = blockIdx.y * 128;
    int colBase = blockIdx.x * 64;
    int tr = t >> 4;   // 0..15 -> rows tr*8..tr*8+7
    int tc = t & 15;   // 0..15 -> cols tc*4..tc*4+3

    // A loader mapping: 8 consecutive elems per thread
    int am = t >> 1;            // 0..127
    int ak = (t & 1) * 8;       // 0 or 8
    const float* Aptr = A + (size_t)(rowBase + am) * K + ak;
    // B loader mapping: one float4 per thread
    int bk = t >> 4;            // 0..15
    int bc = (t & 15) * 4;      // 0..60
    const float* Bptr = Bm + (size_t)bk * Nn + colBase + bc;

    float acc[8][4];
#pragma unroll
    for (int r = 0; r < 8; r++)
#pragma unroll
        for (int c = 0; c < 4; c++) acc[r][c] = 0.f;

    for (int k0 = 0; k0 < K; k0 += 16) {
        float4 a0 = *(const float4*)(Aptr + k0);
        float4 a1 = *(const float4*)(Aptr + k0 + 4);
        float4 b0 = *(const float4*)(Bptr + (size_t)k0 * Nn);

        __syncthreads();
        As[ak + 0][am] = a0.x; As[ak + 1][am] = a0.y;
        As[ak + 2][am] = a0.z; As[ak + 3][am] = a0.w;
        As[ak + 4][am] = a1.x; As[ak + 5][am] = a1.y;
        As[ak + 6][am] = a1.z; As[ak + 7][am] = a1.w;
        *(float4*)&Bs[bk][bc] = b0;
        __syncthreads();

#pragma unroll
        for (int kk = 0; kk < 16; kk++) {
            float ar[8], br[4];
#pragma unroll
            for (int r = 0; r < 8; r++) ar[r] = As[kk][tr * 8 + r];
#pragma unroll
            for (int c = 0; c < 4; c++) br[c] = Bs[kk][tc * 4 + c];
#pragma unroll
            for (int r = 0; r < 8; r++)
#pragma unroll
                for (int c = 0; c < 4; c++) acc[r][c] += ar[r] * br[c];
        }
    }

#pragma unroll
    for (int r = 0; r < 8; r++) {
        float4 v = make_float4(acc[r][0], acc[r][1], acc[r][2], acc[r][3]);
        *(float4*)(C + (size_t)(rowBase + tr * 8 + r) * Nn + colBase + tc * 4) = v;
    }
}

// ---------------------------------------------------------------------------
// Block-sparse attention. One CTA per (block, head). Each thread owns one
// query token (loop if m > 128). Flash-style online softmax over key chunks
// of 32, K/V gathered to smem. Cross-block keys are exactly weight-0 in the
// reference (exp(-1e9 - max) underflows), so iterating only same-block keys
// is numerically equivalent.
// ---------------------------------------------------------------------------
__global__ __launch_bounds__(128) void attn_kernel(const float* __restrict__ mask) {
    int b = blockIdx.x;
    int h = blockIdx.y;
    int m = g_cnt[b];
    if (m == 0) return;
    int off = g_off[b];

    __shared__ float Ks[CHK][HDIM];
    __shared__ float Vs[CHK][HDIM];
    __shared__ float Ss[128][CHK + 1];
    __shared__ float bs[CHK];

    int tid = threadIdx.x;

    for (int q0 = 0; q0 < m; q0 += 128) {
        int qi = q0 + tid;
        bool act = qi < m;
        int qt = act ? g_mem[off + qi] : g_mem[off];

        float qreg[HDIM];
        {
            const float4* qp = (const float4*)(g_Q + (size_t)qt * UNITS + h * HDIM);
#pragma unroll
            for (int i = 0; i < 16; i++) {
                float4 v = qp[i];
                qreg[4 * i + 0] = v.x; qreg[4 * i + 1] = v.y;
                qreg[4 * i + 2] = v.z; qreg[4 * i + 3] = v.w;
            }
        }

        float mx = -3e38f, sm = 0.f;
        float oacc[HDIM];
#pragma unroll
        for (int d = 0; d < HDIM; d++) oacc[d] = 0.f;

        for (int k0 = 0; k0 < m; k0 += CHK) {
            int cn = min(CHK, m - k0);
            __syncthreads();
            // cooperative gather of K/V chunk: 4 threads per key row
            {
                int row = tid >> 2;         // 0..31
                int seg = (tid & 3) * 16;   // 0/16/32/48
                if (row < cn) {
                    int tk = g_mem[off + k0 + row];
                    const float4* kp = (const float4*)(g_K + (size_t)tk * UNITS + h * HDIM + seg);
                    const float4* vp = (const float4*)(g_V + (size_t)tk * UNITS + h * HDIM + seg);
#pragma unroll
                    for (int i = 0; i < 4; i++) {
                        ((float4*)&Ks[row][seg])[i] = kp[i];
                        ((float4*)&Vs[row][seg])[i] = vp[i];
                    }
                    if ((tid & 3) == 0)
                        bs[row] = (1.0f - mask[tk]) * (-1e9f);
                }
            }
            __syncthreads();

            float cm = -3e38f;
            for (int j = 0; j < cn; j++) {
                float s = 0.f;
#pragma unroll
                for (int d = 0; d < HDIM; d++) s += qreg[d] * Ks[j][d];
                s = s * 0.125f + bs[j];
                Ss[tid][j] = s;
                cm = fmaxf(cm, s);
            }
            float nm = fmaxf(mx, cm);
            float corr = __expf(mx - nm);
            sm *= corr;
#pragma unroll
            for (int d = 0; d < HDIM; d++) oacc[d] *= corr;
            for (int j = 0; j < cn; j++) {
                float p = __expf(Ss[tid][j] - nm);
                sm += p;
#pragma unroll
                for (int d = 0; d < HDIM; d++) oacc[d] += p * Vs[j][d];
            }
            mx = nm;
        }

        if (act) {
            float inv = 1.0f / sm;
            float* op = g_O + (size_t)qt * UNITS + h * HDIM;
#pragma unroll
            for (int i = 0; i < 16; i++) {
                float4 v = make_float4(oacc[4 * i + 0] * inv, oacc[4 * i + 1] * inv,
                                       oacc[4 * i + 2] * inv, oacc[4 * i + 3] * inv);
                *(float4*)(op + 4 * i) = v;
            }
        }
    }
}

// ---------------------------------------------------------------------------
extern "C" void kernel_launch(void* const* d_in, const int* in_sizes, int n_in,
                              void* d_out, int out_size)
{
    const float* x    = (const float*)d_in[0];
    const float* Wq   = (const float*)d_in[1];
    const float* Wk   = (const float*)d_in[2];
    const float* Wv   = (const float*)d_in[3];
    const float* Wo   = (const float*)d_in[4];
    const float* mask = (const float*)d_in[5];
    const int*   ids  = (const int*)d_in[6];
    float* out = (float*)d_out;

    float *Q, *K, *V, *O;
    cudaGetSymbolAddress((void**)&Q, g_Q);
    cudaGetSymbolAddress((void**)&K, g_K);
    cudaGetSymbolAddress((void**)&V, g_V);
    cudaGetSymbolAddress((void**)&O, g_O);

    build_index_kernel<<<1, NBLK>>>(ids);

    dim3 gg(UNITS / 64, NTOK / 128);
    sgemm_kernel<<<gg, 256>>>(x, Wq, Q, NTOK, UNITS, UNITS);
    sgemm_kernel<<<gg, 256>>>(x, Wk, K, NTOK, UNITS, UNITS);
    sgemm_kernel<<<gg, 256>>>(x, Wv, V, NTOK, UNITS, UNITS);

    attn_kernel<<<dim3(NBLK, NHEAD), 128>>>(mask);

    sgemm_kernel<<<gg, 256>>>(O, Wo, out, NTOK, UNITS, UNITS);
}

// round 2
// speedup vs baseline: 1.9166x; 1.9166x over previous
#include <cuda_runtime.h>
#include <cuda_bf16.h>
#include <math.h>

#define NTOK  3072
#define UNITS 1024
#define NHEAD 16
#define HDIM  64
#define NBLK  64
#define CHK   32

// Scratch (device globals — no allocation allowed)
__device__ float g_Q[NTOK * UNITS];
__device__ float g_K[NTOK * UNITS];
__device__ float g_V[NTOK * UNITS];
__device__ float g_O[NTOK * UNITS];
__device__ int   g_cnt[NBLK];
__device__ int   g_off[NBLK];
__device__ int   g_mem[NTOK];

// ---------------------------------------------------------------------------
__global__ void build_index_kernel(const int* __restrict__ ids) {
    __shared__ int s_cnt[NBLK];
    int b = threadIdx.x;  // 0..63
    int c = 0;
    for (int i = 0; i < NTOK; i++) c += (ids[i] == b) ? 1 : 0;
    s_cnt[b] = c;
    g_cnt[b] = c;
    __syncthreads();
    if (b == 0) {
        int acc = 0;
        for (int j = 0; j < NBLK; j++) { g_off[j] = acc; acc += s_cnt[j]; }
    }
    __syncthreads();
    int p = g_off[b];
    for (int i = 0; i < NTOK; i++)
        if (ids[i] == b) g_mem[p++] = i;
}

// ---------------------------------------------------------------------------
// TF32 tensor-core GEMM: C[M,N] = A[M,K] @ B[K,N], row-major fp32 in/out.
// BM=128, BN=128, BK=32. 256 threads = 8 warps (2x4), warp tile 64x32.
// K-within-8 permuted storage (pos = 2*(k%4) + k/4) so each mma fragment
// pair (a0,a2)/(a1,a3)/(b0,b1) is a contiguous LDS.64. XOR swizzles make
// both STS and fragment LDS bank-conflict-free.
// ---------------------------------------------------------------------------
__device__ __forceinline__ unsigned f2tf32(float f) {
    unsigned u;
    asm("cvt.rna.tf32.f32 %0, %1;" : "=r"(u) : "f"(f));
    return u;
}

__global__ __launch_bounds__(256, 2) void tf32_gemm(
    const float* __restrict__ A, const float* __restrict__ B,
    float* __restrict__ C, int M, int NN, int K)
{
    __shared__ float As[128 * 40];       // [m][kcol], stride 40
    __shared__ float Bs[4 * 128 * 8];    // [kstep][n][pos]

    const int t    = threadIdx.x;
    const int lane = t & 31;
    const int warp = t >> 5;
    const int wr   = warp >> 2;          // 0..1
    const int wc   = warp & 3;           // 0..3
    const int r    = lane >> 2;          // 0..7
    const int cq   = lane & 3;           // 0..3
    const int rowBase = blockIdx.y * 128;
    const int colBase = blockIdx.x * 128;

    // ---- A loader: thread covers (m = t/8 + 32*mi, k4 = (t&7)*4) ----
    const int am  = t >> 3;              // 0..31
    const int ak4 = (t & 7) * 4;
    const float* Ag = A + (size_t)(rowBase + am) * K + ak4;
    int asts[4];
    {
        int axm = 2 * ((t >> 3) & 3);    // XOR by 2*(m%4)
#pragma unroll
        for (int j = 0; j < 4; j++) {
            int kk = ak4 + j;
            int ksl = kk >> 3, kap = kk & 7;
            int p = 2 * (kap & 3) + (kap >> 2);
            asts[j] = (ksl * 8 + p) ^ axm;
        }
    }

    // ---- B loader: thread covers (k = t/32 + 8*ki, n = lane + 32*ni) ----
    const int bk = t >> 5;               // 0..7
    const float* Bg = B + (size_t)bk * NN + colBase + lane;
    const int pB = (2 * (bk & 3) + (bk >> 2)) ^ (lane >> 2);

    // ---- fragment smem offsets ----
    const int axr = (2 * cq) ^ (2 * (r & 3));
    int aoff[4][2];
#pragma unroll
    for (int i = 0; i < 4; i++) {
        int m0 = wr * 64 + i * 16 + r;
        aoff[i][0] = m0 * 40 + axr;
        aoff[i][1] = (m0 + 8) * 40 + axr;
    }
    int boff[4];
#pragma unroll
    for (int j = 0; j < 4; j++)
        boff[j] = (wc * 32 + j * 8 + r) * 8 + ((2 * cq) ^ (2 * j));
    const bool bswap = ((r >> 2) & 1) != 0;  // lanes 16..31: stored pair swapped

    float acc[4][4][4];
#pragma unroll
    for (int i = 0; i < 4; i++)
#pragma unroll
        for (int j = 0; j < 4; j++)
#pragma unroll
            for (int e = 0; e < 4; e++) acc[i][j][e] = 0.f;

    // ---- prefetch tile 0 ----
    float4 pa[4];
    float  pb[16];
#pragma unroll
    for (int mi = 0; mi < 4; mi++)
        pa[mi] = *(const float4*)(Ag + (size_t)(mi * 32) * K);
#pragma unroll
    for (int ki = 0; ki < 4; ki++)
#pragma unroll
        for (int ni = 0; ni < 4; ni++)
            pb[ki * 4 + ni] = Bg[(size_t)(ki * 8) * NN + ni * 32];

    for (int k0 = 0; k0 < K; k0 += 32) {
        __syncthreads();
        // ---- store tile to smem (with tf32 rounding) ----
#pragma unroll
        for (int mi = 0; mi < 4; mi++) {
            float v[4] = {pa[mi].x, pa[mi].y, pa[mi].z, pa[mi].w};
            int mrow = am + mi * 32;
#pragma unroll
            for (int j = 0; j < 4; j++)
                As[mrow * 40 + asts[j]] = __uint_as_float(f2tf32(v[j]));
        }
#pragma unroll
        for (int ki = 0; ki < 4; ki++)
#pragma unroll
            for (int ni = 0; ni < 4; ni++)
                Bs[ki * 1024 + (lane + ni * 32) * 8 + pB] =
                    __uint_as_float(f2tf32(pb[ki * 4 + ni]));
        __syncthreads();

        // ---- prefetch next tile ----
        if (k0 + 32 < K) {
            const int kn = k0 + 32;
#pragma unroll
            for (int mi = 0; mi < 4; mi++)
                pa[mi] = *(const float4*)(Ag + (size_t)(mi * 32) * K + kn);
#pragma unroll
            for (int ki = 0; ki < 4; ki++)
#pragma unroll
                for (int ni = 0; ni < 4; ni++)
                    pb[ki * 4 + ni] = Bg[(size_t)(kn + ki * 8) * NN + ni * 32];
        }

        // ---- compute ----
#pragma unroll
        for (int ks = 0; ks < 4; ks++) {
            unsigned af[4][4];
#pragma unroll
            for (int i = 0; i < 4; i++) {
                float2 a0 = *(const float2*)&As[aoff[i][0] + ks * 8];
                float2 a1 = *(const float2*)&As[aoff[i][1] + ks * 8];
                af[i][0] = __float_as_uint(a0.x);
                af[i][1] = __float_as_uint(a1.x);
                af[i][2] = __float_as_uint(a0.y);
                af[i][3] = __float_as_uint(a1.y);
            }
            unsigned bf[4][2];
#pragma unroll
            for (int j = 0; j < 4; j++) {
                float2 bv = *(const float2*)&Bs[ks * 1024 + boff[j]];
                float b0 = bswap ? bv.y : bv.x;
                float b1 = bswap ? bv.x : bv.y;
                bf[j][0] = __float_as_uint(b0);
                bf[j][1] = __float_as_uint(b1);
            }
#pragma unroll
            for (int i = 0; i < 4; i++)
#pragma unroll
                for (int j = 0; j < 4; j++) {
                    asm volatile(
                        "mma.sync.aligned.m16n8k8.row.col.f32.tf32.tf32.f32 "
                        "{%0,%1,%2,%3}, {%4,%5,%6,%7}, {%8,%9}, {%0,%1,%2,%3};"
                        : "+f"(acc[i][j][0]), "+f"(acc[i][j][1]),
                          "+f"(acc[i][j][2]), "+f"(acc[i][j][3])
                        : "r"(af[i][0]), "r"(af[i][1]), "r"(af[i][2]), "r"(af[i][3]),
                          "r"(bf[j][0]), "r"(bf[j][1]));
                }
        }
    }

    // ---- epilogue ----
#pragma unroll
    for (int i = 0; i < 4; i++) {
        int row0 = rowBase + wr * 64 + i * 16 + r;
#pragma unroll
        for (int j = 0; j < 4; j++) {
            int col = colBase + wc * 32 + j * 8 + 2 * cq;
            *(float2*)&C[(size_t)row0 * NN + col] =
                make_float2(acc[i][j][0], acc[i][j][1]);
            *(float2*)&C[(size_t)(row0 + 8) * NN + col] =
                make_float2(acc[i][j][2], acc[i][j][3]);
        }
    }
}

// ---------------------------------------------------------------------------
// Block-sparse attention (unchanged from round 1; same-block keys only).
// ---------------------------------------------------------------------------
__global__ __launch_bounds__(128) void attn_kernel(const float* __restrict__ mask) {
    int b = blockIdx.x;
    int h = blockIdx.y;
    int m = g_cnt[b];
    if (m == 0) return;
    int off = g_off[b];

    __shared__ float Ks[CHK][HDIM];
    __shared__ float Vs[CHK][HDIM];
    __shared__ float Ss[128][CHK + 1];
    __shared__ float bs[CHK];

    int tid = threadIdx.x;

    for (int q0 = 0; q0 < m; q0 += 128) {
        int qi = q0 + tid;
        bool act = qi < m;
        int qt = act ? g_mem[off + qi] : g_mem[off];

        float qreg[HDIM];
        {
            const float4* qp = (const float4*)(g_Q + (size_t)qt * UNITS + h * HDIM);
#pragma unroll
            for (int i = 0; i < 16; i++) {
                float4 v = qp[i];
                qreg[4 * i + 0] = v.x; qreg[4 * i + 1] = v.y;
                qreg[4 * i + 2] = v.z; qreg[4 * i + 3] = v.w;
            }
        }

        float mx = -3e38f, sm = 0.f;
        float oacc[HDIM];
#pragma unroll
        for (int d = 0; d < HDIM; d++) oacc[d] = 0.f;

        for (int k0 = 0; k0 < m; k0 += CHK) {
            int cn = min(CHK, m - k0);
            __syncthreads();
            {
                int row = tid >> 2;
                int seg = (tid & 3) * 16;
                if (row < cn) {
                    int tk = g_mem[off + k0 + row];
                    const float4* kp = (const float4*)(g_K + (size_t)tk * UNITS + h * HDIM + seg);
                    const float4* vp = (const float4*)(g_V + (size_t)tk * UNITS + h * HDIM + seg);
#pragma unroll
                    for (int i = 0; i < 4; i++) {
                        ((float4*)&Ks[row][seg])[i] = kp[i];
                        ((float4*)&Vs[row][seg])[i] = vp[i];
                    }
                    if ((tid & 3) == 0)
                        bs[row] = (1.0f - mask[tk]) * (-1e9f);
                }
            }
            __syncthreads();

            float cm = -3e38f;
            for (int j = 0; j < cn; j++) {
                float s = 0.f;
#pragma unroll
                for (int d = 0; d < HDIM; d++) s += qreg[d] * Ks[j][d];
                s = s * 0.125f + bs[j];
                Ss[tid][j] = s;
                cm = fmaxf(cm, s);
            }
            float nm = fmaxf(mx, cm);
            float corr = __expf(mx - nm);
            sm *= corr;
#pragma unroll
            for (int d = 0; d < HDIM; d++) oacc[d] *= corr;
            for (int j = 0; j < cn; j++) {
                float p = __expf(Ss[tid][j] - nm);
                sm += p;
#pragma unroll
                for (int d = 0; d < HDIM; d++) oacc[d] += p * Vs[j][d];
            }
            mx = nm;
        }

        if (act) {
            float inv = 1.0f / sm;
            float* op = g_O + (size_t)qt * UNITS + h * HDIM;
#pragma unroll
            for (int i = 0; i < 16; i++) {
                float4 v = make_float4(oacc[4 * i + 0] * inv, oacc[4 * i + 1] * inv,
                                       oacc[4 * i + 2] * inv, oacc[4 * i + 3] * inv);
                *(float4*)(op + 4 * i) = v;
            }
        }
    }
}

// ---------------------------------------------------------------------------
extern "C" void kernel_launch(void* const* d_in, const int* in_sizes, int n_in,
                              void* d_out, int out_size)
{
    const float* x    = (const float*)d_in[0];
    const float* Wq   = (const float*)d_in[1];
    const float* Wk   = (const float*)d_in[2];
    const float* Wv   = (const float*)d_in[3];
    const float* Wo   = (const float*)d_in[4];
    const float* mask = (const float*)d_in[5];
    const int*   ids  = (const int*)d_in[6];
    float* out = (float*)d_out;

    float *Q, *K, *V, *O;
    cudaGetSymbolAddress((void**)&Q, g_Q);
    cudaGetSymbolAddress((void**)&K, g_K);
    cudaGetSymbolAddress((void**)&V, g_V);
    cudaGetSymbolAddress((void**)&O, g_O);

    build_index_kernel<<<1, NBLK>>>(ids);

    dim3 gg(UNITS / 128, NTOK / 128);
    tf32_gemm<<<gg, 256>>>(x, Wq, Q, NTOK, UNITS, UNITS);
    tf32_gemm<<<gg, 256>>>(x, Wk, K, NTOK, UNITS, UNITS);
    tf32_gemm<<<gg, 256>>>(x, Wv, V, NTOK, UNITS, UNITS);

    attn_kernel<<<dim3(NBLK, NHEAD), 128>>>(mask);

    tf32_gemm<<<gg, 256>>>(O, Wo, out, NTOK, UNITS, UNITS);
}